// round 6
// baseline (speedup 1.0000x reference)
#include <cuda_runtime.h>
#include <cuda_bf16.h>
#include <math.h>
#include <stdint.h>

#define N_TOK     16384
#define IN_STACKS 4
#define IN_DIM    256
#define KDIM      1024
#define OUT_DIM   2048

// GEMM tiling
#define BM 128
#define BN 128
#define BK 16
#define NCHUNK (KDIM / BK)        // 64
#define STRIDE_B 48u              // padded bytes per 16-bf16 row (conflict-free)
#define ARR_BYTES 6144u           // 128 rows * 48B
#define STAGE_BYTES 24576u        // Ahi, Alo, Bhi, Blo
#define STAGES 4
#define SMEM_TOTAL (STAGES * STAGE_BYTES)   // 98304

// ---------------- scratch ----------------
__device__ __nv_bfloat16 g_Ahi[(size_t)N_TOK * KDIM];
__device__ __nv_bfloat16 g_Alo[(size_t)N_TOK * KDIM];
__device__ __nv_bfloat16 g_Bhi[(size_t)OUT_DIM * KDIM];   // W transposed [N,K]
__device__ __nv_bfloat16 g_Blo[(size_t)OUT_DIM * KDIM];
__device__ float  g_cx2[N_TOK];
__device__ float  g_rowsum[N_TOK];
__device__ float4 g_colp[OUT_DIM];

// ---------------- PTX helpers ----------------
__device__ __forceinline__ uint32_t smem_u32(const void* p) {
    uint32_t a;
    asm("{ .reg .u64 t; cvta.to.shared.u64 t, %1; cvt.u32.u64 %0, t; }" : "=r"(a) : "l"(p));
    return a;
}
__device__ __forceinline__ void cp_async16(uint32_t dst, const void* src) {
    asm volatile("cp.async.cg.shared.global [%0], [%1], 16;" :: "r"(dst), "l"(src));
}
__device__ __forceinline__ void cp_commit() { asm volatile("cp.async.commit_group;" ::: "memory"); }
__device__ __forceinline__ void cp_wait2()  { asm volatile("cp.async.wait_group 2;" ::: "memory"); }

__device__ __forceinline__ void ldm4(uint32_t* r, uint32_t addr) {
    asm volatile("ldmatrix.sync.aligned.m8n8.x4.shared.b16 {%0,%1,%2,%3}, [%4];"
                 : "=r"(r[0]), "=r"(r[1]), "=r"(r[2]), "=r"(r[3]) : "r"(addr));
}
__device__ __forceinline__ void mma16816(float* d, const uint32_t* a,
                                         uint32_t b0, uint32_t b1) {
    asm volatile(
        "mma.sync.aligned.m16n8k16.row.col.f32.bf16.bf16.f32 "
        "{%0,%1,%2,%3}, {%4,%5,%6,%7}, {%8,%9}, {%0,%1,%2,%3};"
        : "+f"(d[0]), "+f"(d[1]), "+f"(d[2]), "+f"(d[3])
        : "r"(a[0]), "r"(a[1]), "r"(a[2]), "r"(a[3]), "r"(b0), "r"(b1));
}

// ---------------------------------------------------------------------------
// Kernel A: per-output-column parameters.
// ---------------------------------------------------------------------------
__global__ void colparams_kernel(const float* __restrict__ W,
                                 const float* __restrict__ wg,
                                 const float* __restrict__ bias,
                                 const float* __restrict__ cptr) {
    int j = blockIdx.x * blockDim.x + threadIdx.x;
    if (j >= OUT_DIM) return;
    float c  = cptr[0];
    float rc = sqrtf(c);
    float s = 0.f;
#pragma unroll 8
    for (int k = 0; k < KDIM; k++) {
        float v = W[(size_t)k * OUT_DIM + j];
        s += v * v;
    }
    float invn = 1.f / fmaxf(sqrtf(s), 1e-15f);
    float drcr = 2.f * rc * bias[j];
    float ch = coshf(drcr), sh = sinhf(drcr);
    g_colp[j] = make_float4(2.f * rc * invn * ch, sh, 2.f * wg[j], 0.f);
}

// ---------------------------------------------------------------------------
// Kernel B: per-row preprocess -> bf16 hi/lo split of xb, plus cx2, zero rowsum.
// ---------------------------------------------------------------------------
__global__ void preprocess_kernel(const float* __restrict__ x,
                                  const float* __restrict__ cptr,
                                  float ratio) {
    int row = blockIdx.x;
    int tid = threadIdx.x;          // 256 == IN_DIM
    const float* xr = x + (size_t)row * KDIM;

    float v[IN_STACKS], sq[IN_STACKS];
#pragma unroll
    for (int s = 0; s < IN_STACKS; s++) {
        v[s]  = xr[s * IN_DIM + tid];
        sq[s] = v[s] * v[s];
    }
#pragma unroll
    for (int off = 16; off > 0; off >>= 1) {
#pragma unroll
        for (int s = 0; s < IN_STACKS; s++)
            sq[s] += __shfl_xor_sync(0xFFFFFFFFu, sq[s], off);
    }
    __shared__ float red[8][IN_STACKS];
    int warp = tid >> 5, lane = tid & 31;
    if (lane == 0) {
#pragma unroll
        for (int s = 0; s < IN_STACKS; s++) red[warp][s] = sq[s];
    }
    __syncthreads();

    float c  = cptr[0];
    float rc = sqrtf(c);

    if (tid < IN_STACKS) {
        float t = 0.f;
#pragma unroll
        for (int w = 0; w < 8; w++) t += red[w][tid];
        float n   = fmaxf(sqrtf(t), 1e-15f);
        float th  = tanhf(rc * n);
        float arg = fminf(fminf(th, 1.f - 0.004f), 1.f - 1e-7f);
        float F   = atanhf(arg) / rc;
        red[0][tid] = F / n;
        red[1][tid] = F;
    }
    __syncthreads();

    float F2 = 0.f;
#pragma unroll
    for (int s = 0; s < IN_STACKS; s++) { float F = red[1][s]; F2 += F * F; }
    float wn    = fmaxf(ratio * sqrtf(F2), 1e-15f);
    float th2   = tanhf(rc * wn);
    float m2rc  = fminf(th2, 1.f - 0.004f);
    float gscal = ratio * m2rc / (rc * wn);

    size_t base = (size_t)row * KDIM;
#pragma unroll
    for (int s = 0; s < IN_STACKS; s++) {
        float val = v[s] * red[0][s] * gscal;
        __nv_bfloat16 h = __float2bfloat16(val);
        g_Ahi[base + s * IN_DIM + tid] = h;
        g_Alo[base + s * IN_DIM + tid] = __float2bfloat16(val - __bfloat162float(h));
    }

    if (tid == 0) {
        g_cx2[row]    = m2rc * m2rc;
        g_rowsum[row] = 0.f;
    }
}

// ---------------------------------------------------------------------------
// Kernel B2: transpose W [K,N] -> [N,K] with bf16 hi/lo split.
// ---------------------------------------------------------------------------
__global__ void wsplit_kernel(const float* __restrict__ W) {
    __shared__ float tile[32][33];
    int n0 = blockIdx.x * 32, k0 = blockIdx.y * 32;
    int tx = threadIdx.x, ty = threadIdx.y;   // (32, 8)
#pragma unroll
    for (int r = 0; r < 4; r++)
        tile[ty + r * 8][tx] = W[(size_t)(k0 + ty + r * 8) * OUT_DIM + n0 + tx];
    __syncthreads();
#pragma unroll
    for (int r = 0; r < 4; r++) {
        int n = n0 + ty + r * 8, k = k0 + tx;
        float vv = tile[tx][ty + r * 8];
        __nv_bfloat16 h = __float2bfloat16(vv);
        g_Bhi[(size_t)n * KDIM + k] = h;
        g_Blo[(size_t)n * KDIM + k] = __float2bfloat16(vv - __bfloat162float(h));
    }
}

// ---------------------------------------------------------------------------
// Kernel C: mma.sync bf16x3 GEMM, 128x128x16 chunks, 4-stage cp.async,
// 2 CTAs/SM, single barrier per chunk, fused MLR epilogue.
// ---------------------------------------------------------------------------
__device__ __forceinline__ void load_chunk(uint32_t st, int rowBlk, int colBlk,
                                           int c, int tid) {
    const int k0 = c * BK;
#pragma unroll
    for (int i = 0; i < 4; i++) {
        int u = tid + i * 256;            // 0..1023
        int arr = u >> 8;                 // 0..3
        int w   = u & 255;
        int row = w >> 1;
        int ch  = w & 1;
        uint32_t dst = st + (uint32_t)arr * ARR_BYTES +
                       (uint32_t)row * STRIDE_B + (uint32_t)ch * 16u;
        const __nv_bfloat16* src;
        if      (arr == 0) src = g_Ahi + (size_t)(rowBlk + row) * KDIM + k0 + ch * 8;
        else if (arr == 1) src = g_Alo + (size_t)(rowBlk + row) * KDIM + k0 + ch * 8;
        else if (arr == 2) src = g_Bhi + (size_t)(colBlk + row) * KDIM + k0 + ch * 8;
        else               src = g_Blo + (size_t)(colBlk + row) * KDIM + k0 + ch * 8;
        cp_async16(dst, src);
    }
}

__device__ __forceinline__ float epi_y(float acc, float4 p, float onep,
                                       float inv_m, float inv_rc) {
    float num = fmaf(acc, p.x, -(onep * p.y));
    float t   = num * inv_m;
    float u   = fmaxf(t + sqrtf(fmaf(t, t, 1.f)), 1e-15f);
    float z   = p.z * logf(u);
    float z2  = z * z;
    float sh  = z * fmaf(z2, fmaf(z2, fmaf(z2, 1.9841270e-4f, 8.3333333e-3f),
                                  0.16666667f), 1.f);
    return sh * inv_rc;
}

__global__ __launch_bounds__(256, 2)
void gemm_mma_kernel(const float* __restrict__ cptr, float* __restrict__ out) {
    extern __shared__ char smem[];
    uint32_t sb = smem_u32(smem);
    int tid = threadIdx.x;
    int wid = tid >> 5, lane = tid & 31;
    int warp_m = wid & 3;        // 4 warps over M (32 rows each)
    int warp_n = wid >> 2;       // 2 warps over N (64 cols each)
    int rowBlk = blockIdx.y * BM;
    int colBlk = blockIdx.x * BN;

    float acc[2][8][4];
#pragma unroll
    for (int a = 0; a < 2; a++)
#pragma unroll
        for (int b = 0; b < 8; b++)
#pragma unroll
            for (int e = 0; e < 4; e++) acc[a][b][e] = 0.f;

    // prologue: prefetch chunks 0..2
#pragma unroll
    for (int p = 0; p < 3; p++) {
        load_chunk(sb + (uint32_t)p * STAGE_BYTES, rowBlk, colBlk, p, tid);
        cp_commit();
    }

    uint32_t offA = (uint32_t)(lane & 15) * STRIDE_B + (uint32_t)(lane >> 4) * 16u;
    uint32_t offB = (uint32_t)(((lane >> 4) << 3) + (lane & 7)) * STRIDE_B +
                    (uint32_t)((lane >> 3) & 1) * 16u;
    uint32_t aBase = (uint32_t)(warp_m * 32) * STRIDE_B + offA;
    uint32_t bBase = 2u * ARR_BYTES + (uint32_t)(warp_n * 64) * STRIDE_B + offB;

    for (int c = 0; c < NCHUNK; c++) {
        cp_wait2();                 // chunk c's group complete
        __syncthreads();            // data visible; all warps done with chunk c-1
        if (c + 3 < NCHUNK)
            load_chunk(sb + (uint32_t)((c + 3) & 3) * STAGE_BYTES,
                       rowBlk, colBlk, c + 3, tid);
        cp_commit();                // always commit (possibly empty group)

        uint32_t st = sb + (uint32_t)(c & 3) * STAGE_BYTES;

        uint32_t Ah[2][4], Al[2][4], Bh[4][4], Bl[4][4];
        ldm4(Ah[0], st + aBase);
        ldm4(Ah[1], st + aBase + 16u * STRIDE_B);
#pragma unroll
        for (int bp = 0; bp < 4; bp++)
            ldm4(Bh[bp], st + bBase + (uint32_t)bp * 16u * STRIDE_B);

        // phase 1: Ah * Bh
#pragma unroll
        for (int mt = 0; mt < 2; mt++)
#pragma unroll
            for (int bp = 0; bp < 4; bp++) {
                mma16816(acc[mt][2 * bp + 0], Ah[mt], Bh[bp][0], Bh[bp][1]);
                mma16816(acc[mt][2 * bp + 1], Ah[mt], Bh[bp][2], Bh[bp][3]);
            }

#pragma unroll
        for (int bp = 0; bp < 4; bp++)
            ldm4(Bl[bp], st + ARR_BYTES + bBase + (uint32_t)bp * 16u * STRIDE_B);

        // phase 2: Ah * Bl
#pragma unroll
        for (int mt = 0; mt < 2; mt++)
#pragma unroll
            for (int bp = 0; bp < 4; bp++) {
                mma16816(acc[mt][2 * bp + 0], Ah[mt], Bl[bp][0], Bl[bp][1]);
                mma16816(acc[mt][2 * bp + 1], Ah[mt], Bl[bp][2], Bl[bp][3]);
            }

        ldm4(Al[0], st + ARR_BYTES + aBase);
        ldm4(Al[1], st + ARR_BYTES + aBase + 16u * STRIDE_B);

        // phase 3: Al * Bh
#pragma unroll
        for (int mt = 0; mt < 2; mt++)
#pragma unroll
            for (int bp = 0; bp < 4; bp++) {
                mma16816(acc[mt][2 * bp + 0], Al[mt], Bh[bp][0], Bh[bp][1]);
                mma16816(acc[mt][2 * bp + 1], Al[mt], Bh[bp][2], Bh[bp][3]);
            }
    }

    // ---- fused epilogue ----
    float cc = cptr[0];
    float rc = sqrtf(cc);
    float inv_rc = 1.f / rc;
    int group = lane >> 2, tig = lane & 3;

#pragma unroll
    for (int mt = 0; mt < 2; mt++) {
        int r0 = rowBlk + warp_m * 32 + mt * 16 + group;
        int r1 = r0 + 8;
        float cx0 = g_cx2[r0], cx1 = g_cx2[r1];
        float inv_m0 = 1.f / fmaxf(1.f - cx0, 1e-15f);
        float inv_m1 = 1.f / fmaxf(1.f - cx1, 1e-15f);
        float onep0 = 1.f + cx0, onep1 = 1.f + cx1;
        float rs0 = 0.f, rs1 = 0.f;
#pragma unroll
        for (int nt = 0; nt < 8; nt++) {
            int col = colBlk + warp_n * 64 + nt * 8 + tig * 2;
            float4 p0 = g_colp[col];
            float4 p1 = g_colp[col + 1];
            float y00 = epi_y(acc[mt][nt][0], p0, onep0, inv_m0, inv_rc);
            float y01 = epi_y(acc[mt][nt][1], p1, onep0, inv_m0, inv_rc);
            float y10 = epi_y(acc[mt][nt][2], p0, onep1, inv_m1, inv_rc);
            float y11 = epi_y(acc[mt][nt][3], p1, onep1, inv_m1, inv_rc);
            *(float2*)(out + (size_t)r0 * OUT_DIM + col) = make_float2(y00, y01);
            *(float2*)(out + (size_t)r1 * OUT_DIM + col) = make_float2(y10, y11);
            rs0 = fmaf(y00, y00, fmaf(y01, y01, rs0));
            rs1 = fmaf(y10, y10, fmaf(y11, y11, rs1));
        }
        rs0 += __shfl_xor_sync(0xFFFFFFFFu, rs0, 1);
        rs0 += __shfl_xor_sync(0xFFFFFFFFu, rs0, 2);
        rs1 += __shfl_xor_sync(0xFFFFFFFFu, rs1, 1);
        rs1 += __shfl_xor_sync(0xFFFFFFFFu, rs1, 2);
        if (tig == 0) {
            atomicAdd(&g_rowsum[r0], rs0);
            atomicAdd(&g_rowsum[r1], rs1);
        }
    }
}

// ---------------------------------------------------------------------------
// Kernel D: per-row final scale.
// ---------------------------------------------------------------------------
__global__ void finalize_kernel(const float* __restrict__ cptr,
                                float* __restrict__ out) {
    int row = blockIdx.x;
    float c  = cptr[0];
    float rc = sqrtf(c);
    float s2 = g_rowsum[row];
    float denom = 1.f + sqrtf(fmaf(c, s2, 1.f));
    float scale = 1.f / denom;
    float nrm  = fmaxf(sqrtf(s2) * scale, 1e-15f);
    float maxn = (1.f - 0.004f) / rc;
    if (nrm > maxn) scale *= maxn / nrm;

    float4* o = (float4*)(out + (size_t)row * OUT_DIM);
    for (int idx = threadIdx.x; idx < OUT_DIM / 4; idx += blockDim.x) {
        float4 v = o[idx];
        v.x *= scale; v.y *= scale; v.z *= scale; v.w *= scale;
        o[idx] = v;
    }
}

// ---------------------------------------------------------------------------
extern "C" void kernel_launch(void* const* d_in, const int* in_sizes, int n_in,
                              void* d_out, int out_size) {
    const float* x    = (const float*)d_in[0];
    const float* wg   = (const float*)d_in[1];
    const float* wv   = (const float*)d_in[2];
    const float* bias = (const float*)d_in[3];
    const float* cptr = (const float*)d_in[4];
    float* out = (float*)d_out;

    double bni = exp(lgamma((double)IN_DIM / 2.0) + lgamma(0.5) -
                     lgamma((double)IN_DIM / 2.0 + 0.5));
    double bn  = exp(lgamma((double)(IN_DIM * IN_STACKS) / 2.0) + lgamma(0.5) -
                     lgamma((double)(IN_DIM * IN_STACKS) / 2.0 + 0.5));
    float ratio = (float)(bn / bni);

    static int smem_set = 0;
    if (!smem_set) {
        cudaFuncSetAttribute(gemm_mma_kernel,
                             cudaFuncAttributeMaxDynamicSharedMemorySize, SMEM_TOTAL);
        smem_set = 1;
    }

    colparams_kernel<<<OUT_DIM / 256, 256>>>(wv, wg, bias, cptr);
    preprocess_kernel<<<N_TOK, 256>>>(x, cptr, ratio);
    wsplit_kernel<<<dim3(OUT_DIM / 32, KDIM / 32), dim3(32, 8)>>>(wv);
    dim3 grid(OUT_DIM / BN, N_TOK / BM);
    gemm_mma_kernel<<<grid, 256, SMEM_TOTAL>>>(cptr, out);
    finalize_kernel<<<N_TOK, 256>>>(cptr, out);
}

// round 7
// speedup vs baseline: 1.0458x; 1.0458x over previous
#include <cuda_runtime.h>
#include <cuda_bf16.h>
#include <math.h>
#include <stdint.h>

#define N_TOK     16384
#define IN_STACKS 4
#define IN_DIM    256
#define KDIM      1024
#define OUT_DIM   2048

// GEMM tiling
#define BM 128
#define BN 128
#define BK 32
#define NCHUNK (KDIM / BK)        // 32
#define STRIDE_B 80u              // padded bytes per 32-bf16 row
#define ARR_BYTES 10240u          // 128 rows * 80B
#define STAGE_BYTES 40960u        // Ahi, Alo, Bhi, Blo
#define STAGES 2
#define SMEM_TOTAL (STAGES * STAGE_BYTES)   // 81920

// ---------------- scratch ----------------
__device__ __nv_bfloat16 g_Ahi[(size_t)N_TOK * KDIM];
__device__ __nv_bfloat16 g_Alo[(size_t)N_TOK * KDIM];
__device__ __nv_bfloat16 g_Bhi[(size_t)OUT_DIM * KDIM];   // W transposed [N,K]
__device__ __nv_bfloat16 g_Blo[(size_t)OUT_DIM * KDIM];
__device__ float  g_cx2[N_TOK];
__device__ float  g_rowsum[N_TOK];
__device__ float4 g_colp[OUT_DIM];

// ---------------- PTX helpers ----------------
__device__ __forceinline__ uint32_t smem_u32(const void* p) {
    uint32_t a;
    asm("{ .reg .u64 t; cvta.to.shared.u64 t, %1; cvt.u32.u64 %0, t; }" : "=r"(a) : "l"(p));
    return a;
}
__device__ __forceinline__ void cp_async16(uint32_t dst, const void* src) {
    asm volatile("cp.async.cg.shared.global [%0], [%1], 16;" :: "r"(dst), "l"(src));
}
__device__ __forceinline__ void cp_commit() { asm volatile("cp.async.commit_group;" ::: "memory"); }
__device__ __forceinline__ void cp_wait1()  { asm volatile("cp.async.wait_group 1;" ::: "memory"); }
__device__ __forceinline__ void cp_wait0()  { asm volatile("cp.async.wait_group 0;" ::: "memory"); }

__device__ __forceinline__ void ldm4(uint32_t* r, uint32_t addr) {
    asm volatile("ldmatrix.sync.aligned.m8n8.x4.shared.b16 {%0,%1,%2,%3}, [%4];"
                 : "=r"(r[0]), "=r"(r[1]), "=r"(r[2]), "=r"(r[3]) : "r"(addr));
}
__device__ __forceinline__ void mma16816(float* d, const uint32_t* a,
                                         uint32_t b0, uint32_t b1) {
    asm volatile(
        "mma.sync.aligned.m16n8k16.row.col.f32.bf16.bf16.f32 "
        "{%0,%1,%2,%3}, {%4,%5,%6,%7}, {%8,%9}, {%0,%1,%2,%3};"
        : "+f"(d[0]), "+f"(d[1]), "+f"(d[2]), "+f"(d[3])
        : "r"(a[0]), "r"(a[1]), "r"(a[2]), "r"(a[3]), "r"(b0), "r"(b1));
}

// ---------------------------------------------------------------------------
// Kernel A: per-output-column parameters.
// ---------------------------------------------------------------------------
__global__ void colparams_kernel(const float* __restrict__ W,
                                 const float* __restrict__ wg,
                                 const float* __restrict__ bias,
                                 const float* __restrict__ cptr) {
    int j = blockIdx.x * blockDim.x + threadIdx.x;
    if (j >= OUT_DIM) return;
    float c  = cptr[0];
    float rc = sqrtf(c);
    float s = 0.f;
#pragma unroll 8
    for (int k = 0; k < KDIM; k++) {
        float v = W[(size_t)k * OUT_DIM + j];
        s += v * v;
    }
    float invn = 1.f / fmaxf(sqrtf(s), 1e-15f);
    float drcr = 2.f * rc * bias[j];
    float ch = coshf(drcr), sh = sinhf(drcr);
    g_colp[j] = make_float4(2.f * rc * invn * ch, sh, 2.f * wg[j], 0.f);
}

// ---------------------------------------------------------------------------
// Kernel B: per-row preprocess -> bf16 hi/lo split of xb, plus cx2, zero rowsum.
// ---------------------------------------------------------------------------
__global__ void preprocess_kernel(const float* __restrict__ x,
                                  const float* __restrict__ cptr,
                                  float ratio) {
    int row = blockIdx.x;
    int tid = threadIdx.x;          // 256 == IN_DIM
    const float* xr = x + (size_t)row * KDIM;

    float v[IN_STACKS], sq[IN_STACKS];
#pragma unroll
    for (int s = 0; s < IN_STACKS; s++) {
        v[s]  = xr[s * IN_DIM + tid];
        sq[s] = v[s] * v[s];
    }
#pragma unroll
    for (int off = 16; off > 0; off >>= 1) {
#pragma unroll
        for (int s = 0; s < IN_STACKS; s++)
            sq[s] += __shfl_xor_sync(0xFFFFFFFFu, sq[s], off);
    }
    __shared__ float red[8][IN_STACKS];
    int warp = tid >> 5, lane = tid & 31;
    if (lane == 0) {
#pragma unroll
        for (int s = 0; s < IN_STACKS; s++) red[warp][s] = sq[s];
    }
    __syncthreads();

    float c  = cptr[0];
    float rc = sqrtf(c);

    if (tid < IN_STACKS) {
        float t = 0.f;
#pragma unroll
        for (int w = 0; w < 8; w++) t += red[w][tid];
        float n   = fmaxf(sqrtf(t), 1e-15f);
        float th  = tanhf(rc * n);
        float arg = fminf(fminf(th, 1.f - 0.004f), 1.f - 1e-7f);
        float F   = atanhf(arg) / rc;
        red[0][tid] = F / n;
        red[1][tid] = F;
    }
    __syncthreads();

    float F2 = 0.f;
#pragma unroll
    for (int s = 0; s < IN_STACKS; s++) { float F = red[1][s]; F2 += F * F; }
    float wn    = fmaxf(ratio * sqrtf(F2), 1e-15f);
    float th2   = tanhf(rc * wn);
    float m2rc  = fminf(th2, 1.f - 0.004f);
    float gscal = ratio * m2rc / (rc * wn);

    size_t base = (size_t)row * KDIM;
#pragma unroll
    for (int s = 0; s < IN_STACKS; s++) {
        float val = v[s] * red[0][s] * gscal;
        __nv_bfloat16 h = __float2bfloat16(val);
        g_Ahi[base + s * IN_DIM + tid] = h;
        g_Alo[base + s * IN_DIM + tid] = __float2bfloat16(val - __bfloat162float(h));
    }

    if (tid == 0) {
        g_cx2[row]    = m2rc * m2rc;
        g_rowsum[row] = 0.f;
    }
}

// ---------------------------------------------------------------------------
// Kernel B2: transpose W [K,N] -> [N,K] with bf16 hi/lo split.
// ---------------------------------------------------------------------------
__global__ void wsplit_kernel(const float* __restrict__ W) {
    __shared__ float tile[32][33];
    int n0 = blockIdx.x * 32, k0 = blockIdx.y * 32;
    int tx = threadIdx.x, ty = threadIdx.y;   // (32, 8)
#pragma unroll
    for (int r = 0; r < 4; r++)
        tile[ty + r * 8][tx] = W[(size_t)(k0 + ty + r * 8) * OUT_DIM + n0 + tx];
    __syncthreads();
#pragma unroll
    for (int r = 0; r < 4; r++) {
        int n = n0 + ty + r * 8, k = k0 + tx;
        float vv = tile[tx][ty + r * 8];
        __nv_bfloat16 h = __float2bfloat16(vv);
        g_Bhi[(size_t)n * KDIM + k] = h;
        g_Blo[(size_t)n * KDIM + k] = __float2bfloat16(vv - __bfloat162float(h));
    }
}

// ---------------------------------------------------------------------------
// Kernel C: mma.sync bf16x3 GEMM (128x128x32 tiles, 2-stage cp.async,
// 2 CTAs/SM), separate Bl regs, interleaved ldmatrix, fused MLR epilogue.
// ---------------------------------------------------------------------------
__device__ __forceinline__ void load_chunk(uint32_t st, int rowBlk, int colBlk,
                                           int c, int tid) {
    const int k0 = c * BK;
#pragma unroll
    for (int i = 0; i < 8; i++) {
        int u = tid + (i & 1) * 256;      // 0..511
        int row = u >> 2;
        int ch  = u & 3;
        uint32_t dst = st + (uint32_t)(i >> 1) * ARR_BYTES +
                       (uint32_t)row * STRIDE_B + (uint32_t)ch * 16u;
        const __nv_bfloat16* src;
        if      ((i >> 1) == 0) src = g_Ahi + (size_t)(rowBlk + row) * KDIM + k0 + ch * 8;
        else if ((i >> 1) == 1) src = g_Alo + (size_t)(rowBlk + row) * KDIM + k0 + ch * 8;
        else if ((i >> 1) == 2) src = g_Bhi + (size_t)(colBlk + row) * KDIM + k0 + ch * 8;
        else                    src = g_Blo + (size_t)(colBlk + row) * KDIM + k0 + ch * 8;
        cp_async16(dst, src);
    }
}

__device__ __forceinline__ float epi_y(float acc, float4 p, float onep,
                                       float inv_m, float inv_rc) {
    float num = fmaf(acc, p.x, -(onep * p.y));
    float t   = num * inv_m;
    float u   = fmaxf(t + sqrtf(fmaf(t, t, 1.f)), 1e-15f);
    float z   = p.z * logf(u);
    float z2  = z * z;
    float sh  = z * fmaf(z2, fmaf(z2, fmaf(z2, 1.9841270e-4f, 8.3333333e-3f),
                                  0.16666667f), 1.f);
    return sh * inv_rc;
}

__global__ __launch_bounds__(256, 2)
void gemm_mma_kernel(const float* __restrict__ cptr, float* __restrict__ out) {
    extern __shared__ char smem[];
    uint32_t sb = smem_u32(smem);
    int tid = threadIdx.x;
    int wid = tid >> 5, lane = tid & 31;
    int warp_m = wid & 3;        // 4 warps over M (32 rows each)
    int warp_n = wid >> 2;       // 2 warps over N (64 cols each)
    int rowBlk = blockIdx.y * BM;
    int colBlk = blockIdx.x * BN;

    float acc[2][8][4];
#pragma unroll
    for (int a = 0; a < 2; a++)
#pragma unroll
        for (int b = 0; b < 8; b++)
#pragma unroll
            for (int e = 0; e < 4; e++) acc[a][b][e] = 0.f;

    load_chunk(sb, rowBlk, colBlk, 0, tid);
    cp_commit();

    uint32_t offA = (uint32_t)(lane & 15) * STRIDE_B + (uint32_t)(lane >> 4) * 16u;
    uint32_t offB = (uint32_t)(((lane >> 4) << 3) + (lane & 7)) * STRIDE_B +
                    (uint32_t)((lane >> 3) & 1) * 16u;
    uint32_t aBase = (uint32_t)(warp_m * 32) * STRIDE_B + offA;
    uint32_t bBase = 2u * ARR_BYTES + (uint32_t)(warp_n * 64) * STRIDE_B + offB;

    for (int c = 0; c < NCHUNK; c++) {
        if (c + 1 < NCHUNK) {
            load_chunk(sb + (uint32_t)((c + 1) & 1) * STAGE_BYTES,
                       rowBlk, colBlk, c + 1, tid);
            cp_commit();
            cp_wait1();
        } else {
            cp_wait0();
        }
        __syncthreads();
        uint32_t st = sb + (uint32_t)(c & 1) * STAGE_BYTES;

#pragma unroll
        for (int ks = 0; ks < 2; ks++) {
            uint32_t kb = (uint32_t)ks * 32u;
            uint32_t Ah[2][4], Al[2][4], Bh[4][4], Bl[4][4];
            // head loads: Ah + Bh
            ldm4(Ah[0], st + aBase + kb);
            ldm4(Ah[1], st + aBase + kb + 16u * STRIDE_B);
#pragma unroll
            for (int bp = 0; bp < 4; bp++)
                ldm4(Bh[bp], st + bBase + kb + (uint32_t)bp * 16u * STRIDE_B);

            // phase 1: Ah * Bh  (hides the Bl loads issued after)
#pragma unroll
            for (int mt = 0; mt < 2; mt++)
#pragma unroll
                for (int bp = 0; bp < 4; bp++) {
                    mma16816(acc[mt][2 * bp + 0], Ah[mt], Bh[bp][0], Bh[bp][1]);
                    mma16816(acc[mt][2 * bp + 1], Ah[mt], Bh[bp][2], Bh[bp][3]);
                }

#pragma unroll
            for (int bp = 0; bp < 4; bp++)
                ldm4(Bl[bp], st + ARR_BYTES + bBase + kb +
                             (uint32_t)bp * 16u * STRIDE_B);

            // phase 2: Ah * Bl
#pragma unroll
            for (int mt = 0; mt < 2; mt++)
#pragma unroll
                for (int bp = 0; bp < 4; bp++) {
                    mma16816(acc[mt][2 * bp + 0], Ah[mt], Bl[bp][0], Bl[bp][1]);
                    mma16816(acc[mt][2 * bp + 1], Ah[mt], Bl[bp][2], Bl[bp][3]);
                }

            ldm4(Al[0], st + ARR_BYTES + aBase + kb);
            ldm4(Al[1], st + ARR_BYTES + aBase + kb + 16u * STRIDE_B);

            // phase 3: Al * Bh
#pragma unroll
            for (int mt = 0; mt < 2; mt++)
#pragma unroll
                for (int bp = 0; bp < 4; bp++) {
                    mma16816(acc[mt][2 * bp + 0], Al[mt], Bh[bp][0], Bh[bp][1]);
                    mma16816(acc[mt][2 * bp + 1], Al[mt], Bh[bp][2], Bh[bp][3]);
                }
        }
        __syncthreads();
    }

    // ---- fused epilogue ----
    float cc = cptr[0];
    float rc = sqrtf(cc);
    float inv_rc = 1.f / rc;
    int group = lane >> 2, tig = lane & 3;

#pragma unroll
    for (int mt = 0; mt < 2; mt++) {
        int r0 = rowBlk + warp_m * 32 + mt * 16 + group;
        int r1 = r0 + 8;
        float cx0 = g_cx2[r0], cx1 = g_cx2[r1];
        float inv_m0 = 1.f / fmaxf(1.f - cx0, 1e-15f);
        float inv_m1 = 1.f / fmaxf(1.f - cx1, 1e-15f);
        float onep0 = 1.f + cx0, onep1 = 1.f + cx1;
        float rs0 = 0.f, rs1 = 0.f;
#pragma unroll
        for (int nt = 0; nt < 8; nt++) {
            int col = colBlk + warp_n * 64 + nt * 8 + tig * 2;
            float4 p0 = g_colp[col];
            float4 p1 = g_colp[col + 1];
            float y00 = epi_y(acc[mt][nt][0], p0, onep0, inv_m0, inv_rc);
            float y01 = epi_y(acc[mt][nt][1], p1, onep0, inv_m0, inv_rc);
            float y10 = epi_y(acc[mt][nt][2], p0, onep1, inv_m1, inv_rc);
            float y11 = epi_y(acc[mt][nt][3], p1, onep1, inv_m1, inv_rc);
            *(float2*)(out + (size_t)r0 * OUT_DIM + col) = make_float2(y00, y01);
            *(float2*)(out + (size_t)r1 * OUT_DIM + col) = make_float2(y10, y11);
            rs0 = fmaf(y00, y00, fmaf(y01, y01, rs0));
            rs1 = fmaf(y10, y10, fmaf(y11, y11, rs1));
        }
        rs0 += __shfl_xor_sync(0xFFFFFFFFu, rs0, 1);
        rs0 += __shfl_xor_sync(0xFFFFFFFFu, rs0, 2);
        rs1 += __shfl_xor_sync(0xFFFFFFFFu, rs1, 1);
        rs1 += __shfl_xor_sync(0xFFFFFFFFu, rs1, 2);
        if (tig == 0) {
            atomicAdd(&g_rowsum[r0], rs0);
            atomicAdd(&g_rowsum[r1], rs1);
        }
    }
}

// ---------------------------------------------------------------------------
// Kernel D: per-row final scale.
// ---------------------------------------------------------------------------
__global__ void finalize_kernel(const float* __restrict__ cptr,
                                float* __restrict__ out) {
    int row = blockIdx.x;
    float c  = cptr[0];
    float rc = sqrtf(c);
    float s2 = g_rowsum[row];
    float denom = 1.f + sqrtf(fmaf(c, s2, 1.f));
    float scale = 1.f / denom;
    float nrm  = fmaxf(sqrtf(s2) * scale, 1e-15f);
    float maxn = (1.f - 0.004f) / rc;
    if (nrm > maxn) scale *= maxn / nrm;

    float4* o = (float4*)(out + (size_t)row * OUT_DIM);
    for (int idx = threadIdx.x; idx < OUT_DIM / 4; idx += blockDim.x) {
        float4 v = o[idx];
        v.x *= scale; v.y *= scale; v.z *= scale; v.w *= scale;
        o[idx] = v;
    }
}

// ---------------------------------------------------------------------------
extern "C" void kernel_launch(void* const* d_in, const int* in_sizes, int n_in,
                              void* d_out, int out_size) {
    const float* x    = (const float*)d_in[0];
    const float* wg   = (const float*)d_in[1];
    const float* wv   = (const float*)d_in[2];
    const float* bias = (const float*)d_in[3];
    const float* cptr = (const float*)d_in[4];
    float* out = (float*)d_out;

    double bni = exp(lgamma((double)IN_DIM / 2.0) + lgamma(0.5) -
                     lgamma((double)IN_DIM / 2.0 + 0.5));
    double bn  = exp(lgamma((double)(IN_DIM * IN_STACKS) / 2.0) + lgamma(0.5) -
                     lgamma((double)(IN_DIM * IN_STACKS) / 2.0 + 0.5));
    float ratio = (float)(bn / bni);

    static int smem_set = 0;
    if (!smem_set) {
        cudaFuncSetAttribute(gemm_mma_kernel,
                             cudaFuncAttributeMaxDynamicSharedMemorySize, SMEM_TOTAL);
        smem_set = 1;
    }

    colparams_kernel<<<OUT_DIM / 256, 256>>>(wv, wg, bias, cptr);
    preprocess_kernel<<<N_TOK, 256>>>(x, cptr, ratio);
    wsplit_kernel<<<dim3(OUT_DIM / 32, KDIM / 32), dim3(32, 8)>>>(wv);
    dim3 grid(OUT_DIM / BN, N_TOK / BM);
    gemm_mma_kernel<<<grid, 256, SMEM_TOTAL>>>(cptr, out);
    finalize_kernel<<<N_TOK, 256>>>(cptr, out);
}

// round 8
// speedup vs baseline: 1.9665x; 1.8804x over previous
#include <cuda_runtime.h>
#include <cuda_fp16.h>
#include <math.h>
#include <stdint.h>

#define N_TOK     16384
#define IN_STACKS 4
#define IN_DIM    256
#define KDIM      1024
#define OUT_DIM   2048

// GEMM tiling: single-product fp16
#define BM 128
#define BN 128
#define BK 64
#define NCHUNK (KDIM / BK)        // 16
#define STRIDE_B 144u             // padded bytes per 64-fp16 row (conflict-free)
#define ARR_BYTES 18432u          // 128 rows * 144B
#define STAGE_BYTES 36864u        // A + B
#define STAGES 3
#define SMEM_TOTAL (STAGES * STAGE_BYTES)   // 110592

#define A_SCALE 16.0f
#define B_SCALE 256.0f
#define INV_AB_SCALE (1.0f / 4096.0f)

// ---------------- scratch ----------------
__device__ __half g_A[(size_t)N_TOK * KDIM];     // xb * 16, fp16
__device__ __half g_B[(size_t)OUT_DIM * KDIM];   // W^T * 256, fp16
__device__ float  g_cx2[N_TOK];
__device__ float  g_rowsum[N_TOK];
__device__ float4 g_colp[OUT_DIM];

// ---------------- PTX helpers ----------------
__device__ __forceinline__ uint32_t smem_u32(const void* p) {
    uint32_t a;
    asm("{ .reg .u64 t; cvta.to.shared.u64 t, %1; cvt.u32.u64 %0, t; }" : "=r"(a) : "l"(p));
    return a;
}
__device__ __forceinline__ void cp_async16(uint32_t dst, const void* src) {
    asm volatile("cp.async.cg.shared.global [%0], [%1], 16;" :: "r"(dst), "l"(src));
}
__device__ __forceinline__ void cp_commit() { asm volatile("cp.async.commit_group;" ::: "memory"); }
__device__ __forceinline__ void cp_wait1()  { asm volatile("cp.async.wait_group 1;" ::: "memory"); }
__device__ __forceinline__ void cp_wait0()  { asm volatile("cp.async.wait_group 0;" ::: "memory"); }

__device__ __forceinline__ void ldm4(uint32_t* r, uint32_t addr) {
    asm volatile("ldmatrix.sync.aligned.m8n8.x4.shared.b16 {%0,%1,%2,%3}, [%4];"
                 : "=r"(r[0]), "=r"(r[1]), "=r"(r[2]), "=r"(r[3]) : "r"(addr));
}
__device__ __forceinline__ void mma16816(float* d, const uint32_t* a,
                                         uint32_t b0, uint32_t b1) {
    asm volatile(
        "mma.sync.aligned.m16n8k16.row.col.f32.f16.f16.f32 "
        "{%0,%1,%2,%3}, {%4,%5,%6,%7}, {%8,%9}, {%0,%1,%2,%3};"
        : "+f"(d[0]), "+f"(d[1]), "+f"(d[2]), "+f"(d[3])
        : "r"(a[0]), "r"(a[1]), "r"(a[2]), "r"(a[3]), "r"(b0), "r"(b1));
}

// ---------------------------------------------------------------------------
// Kernel A: per-output-column parameters (p.x absorbs the 1/4096 GEMM scale).
// ---------------------------------------------------------------------------
__global__ void colparams_kernel(const float* __restrict__ W,
                                 const float* __restrict__ wg,
                                 const float* __restrict__ bias,
                                 const float* __restrict__ cptr) {
    int j = blockIdx.x * blockDim.x + threadIdx.x;
    if (j >= OUT_DIM) return;
    float c  = cptr[0];
    float rc = sqrtf(c);
    float s = 0.f;
#pragma unroll 8
    for (int k = 0; k < KDIM; k++) {
        float v = W[(size_t)k * OUT_DIM + j];
        s += v * v;
    }
    float invn = 1.f / fmaxf(sqrtf(s), 1e-15f);
    float drcr = 2.f * rc * bias[j];
    float ch = coshf(drcr), sh = sinhf(drcr);
    g_colp[j] = make_float4(2.f * rc * invn * ch * INV_AB_SCALE, sh, 2.f * wg[j], 0.f);
}

// ---------------------------------------------------------------------------
// Kernel B: per-row preprocess -> fp16 xb (scaled x16), cx2, zero rowsum.
// ---------------------------------------------------------------------------
__global__ void preprocess_kernel(const float* __restrict__ x,
                                  const float* __restrict__ cptr,
                                  float ratio) {
    int row = blockIdx.x;
    int tid = threadIdx.x;          // 256 == IN_DIM
    const float* xr = x + (size_t)row * KDIM;

    float v[IN_STACKS], sq[IN_STACKS];
#pragma unroll
    for (int s = 0; s < IN_STACKS; s++) {
        v[s]  = xr[s * IN_DIM + tid];
        sq[s] = v[s] * v[s];
    }
#pragma unroll
    for (int off = 16; off > 0; off >>= 1) {
#pragma unroll
        for (int s = 0; s < IN_STACKS; s++)
            sq[s] += __shfl_xor_sync(0xFFFFFFFFu, sq[s], off);
    }
    __shared__ float red[8][IN_STACKS];
    int warp = tid >> 5, lane = tid & 31;
    if (lane == 0) {
#pragma unroll
        for (int s = 0; s < IN_STACKS; s++) red[warp][s] = sq[s];
    }
    __syncthreads();

    float c  = cptr[0];
    float rc = sqrtf(c);

    if (tid < IN_STACKS) {
        float t = 0.f;
#pragma unroll
        for (int w = 0; w < 8; w++) t += red[w][tid];
        float n   = fmaxf(sqrtf(t), 1e-15f);
        float th  = tanhf(rc * n);
        float arg = fminf(fminf(th, 1.f - 0.004f), 1.f - 1e-7f);
        float F   = atanhf(arg) / rc;
        red[0][tid] = F / n;
        red[1][tid] = F;
    }
    __syncthreads();

    float F2 = 0.f;
#pragma unroll
    for (int s = 0; s < IN_STACKS; s++) { float F = red[1][s]; F2 += F * F; }
    float wn    = fmaxf(ratio * sqrtf(F2), 1e-15f);
    float th2   = tanhf(rc * wn);
    float m2rc  = fminf(th2, 1.f - 0.004f);
    float gscal = ratio * m2rc / (rc * wn);

    size_t base = (size_t)row * KDIM;
#pragma unroll
    for (int s = 0; s < IN_STACKS; s++) {
        float val = v[s] * red[0][s] * gscal;
        g_A[base + s * IN_DIM + tid] = __float2half_rn(val * A_SCALE);
    }

    if (tid == 0) {
        g_cx2[row]    = m2rc * m2rc;
        g_rowsum[row] = 0.f;
    }
}

// ---------------------------------------------------------------------------
// Kernel B2: transpose W [K,N] -> [N,K] fp16 (scaled x256).
// ---------------------------------------------------------------------------
__global__ void wsplit_kernel(const float* __restrict__ W) {
    __shared__ float tile[32][33];
    int n0 = blockIdx.x * 32, k0 = blockIdx.y * 32;
    int tx = threadIdx.x, ty = threadIdx.y;   // (32, 8)
#pragma unroll
    for (int r = 0; r < 4; r++)
        tile[ty + r * 8][tx] = W[(size_t)(k0 + ty + r * 8) * OUT_DIM + n0 + tx];
    __syncthreads();
#pragma unroll
    for (int r = 0; r < 4; r++) {
        int n = n0 + ty + r * 8, k = k0 + tx;
        g_B[(size_t)n * KDIM + k] = __float2half_rn(tile[tx][ty + r * 8] * B_SCALE);
    }
}

// ---------------------------------------------------------------------------
// Kernel C: fp16 single-product GEMM (128x128x64 chunks, 3-stage cp.async,
// single barrier per chunk, 2 CTAs/SM) with fused MLR epilogue.
// ---------------------------------------------------------------------------
__device__ __forceinline__ void load_chunk(uint32_t st, int rowBlk, int colBlk,
                                           int c, int tid) {
    const int k0 = c * BK;
#pragma unroll
    for (int i = 0; i < 8; i++) {
        int u = tid + i * 256;            // 0..2047
        int arr = u >> 10;                // 0: A, 1: B
        int w   = u & 1023;
        int row = w >> 3;
        int ch  = w & 7;
        uint32_t dst = st + (uint32_t)arr * ARR_BYTES +
                       (uint32_t)row * STRIDE_B + (uint32_t)ch * 16u;
        const __half* src = arr ? (g_B + (size_t)(colBlk + row) * KDIM + k0 + ch * 8)
                                : (g_A + (size_t)(rowBlk + row) * KDIM + k0 + ch * 8);
        cp_async16(dst, src);
    }
}

__device__ __forceinline__ float epi_y(float acc, float4 p, float onep,
                                       float inv_m, float inv_rc) {
    float num = fmaf(acc, p.x, -(onep * p.y));
    float t   = num * inv_m;
    float u   = fmaxf(t + sqrtf(fmaf(t, t, 1.f)), 1e-15f);
    float z   = p.z * logf(u);
    float z2  = z * z;
    float sh  = z * fmaf(z2, fmaf(z2, fmaf(z2, 1.9841270e-4f, 8.3333333e-3f),
                                  0.16666667f), 1.f);
    return sh * inv_rc;
}

__global__ __launch_bounds__(256, 2)
void gemm_mma_kernel(const float* __restrict__ cptr, float* __restrict__ out) {
    extern __shared__ char smem[];
    uint32_t sb = smem_u32(smem);
    int tid = threadIdx.x;
    int wid = tid >> 5, lane = tid & 31;
    int warp_m = wid & 3;        // 4 warps over M (32 rows each)
    int warp_n = wid >> 2;       // 2 warps over N (64 cols each)
    int rowBlk = blockIdx.y * BM;
    int colBlk = blockIdx.x * BN;

    float acc[2][8][4];
#pragma unroll
    for (int a = 0; a < 2; a++)
#pragma unroll
        for (int b = 0; b < 8; b++)
#pragma unroll
            for (int e = 0; e < 4; e++) acc[a][b][e] = 0.f;

    load_chunk(sb + 0 * STAGE_BYTES, rowBlk, colBlk, 0, tid); cp_commit();
    load_chunk(sb + 1 * STAGE_BYTES, rowBlk, colBlk, 1, tid); cp_commit();

    uint32_t offA = (uint32_t)(lane & 15) * STRIDE_B + (uint32_t)(lane >> 4) * 16u;
    uint32_t offB = (uint32_t)(((lane >> 4) << 3) + (lane & 7)) * STRIDE_B +
                    (uint32_t)((lane >> 3) & 1) * 16u;
    uint32_t aBase = (uint32_t)(warp_m * 32) * STRIDE_B + offA;
    uint32_t bBase = ARR_BYTES + (uint32_t)(warp_n * 64) * STRIDE_B + offB;

    int stage = 0;
    for (int c = 0; c < NCHUNK; c++) {
        if (c == NCHUNK - 1) cp_wait0(); else cp_wait1();
        __syncthreads();           // chunk c visible; compute(c-1) done everywhere
        if (c + 2 < NCHUNK) {
            int ns = stage + 2; if (ns >= 3) ns -= 3;
            load_chunk(sb + (uint32_t)ns * STAGE_BYTES, rowBlk, colBlk, c + 2, tid);
            cp_commit();
        }
        uint32_t st = sb + (uint32_t)stage * STAGE_BYTES;
        if (++stage == 3) stage = 0;

#pragma unroll
        for (int ks = 0; ks < 4; ks++) {
            uint32_t kb = (uint32_t)ks * 32u;
            uint32_t A[2][4], B[4][4];
            ldm4(A[0], st + aBase + kb);
            ldm4(A[1], st + aBase + kb + 16u * STRIDE_B);
#pragma unroll
            for (int bp = 0; bp < 4; bp++)
                ldm4(B[bp], st + bBase + kb + (uint32_t)bp * 16u * STRIDE_B);
#pragma unroll
            for (int mt = 0; mt < 2; mt++)
#pragma unroll
                for (int bp = 0; bp < 4; bp++) {
                    mma16816(acc[mt][2 * bp + 0], A[mt], B[bp][0], B[bp][1]);
                    mma16816(acc[mt][2 * bp + 1], A[mt], B[bp][2], B[bp][3]);
                }
        }
    }

    // ---- fused epilogue ----
    float cc = cptr[0];
    float rc = sqrtf(cc);
    float inv_rc = 1.f / rc;
    int group = lane >> 2, tig = lane & 3;

#pragma unroll
    for (int mt = 0; mt < 2; mt++) {
        int r0 = rowBlk + warp_m * 32 + mt * 16 + group;
        int r1 = r0 + 8;
        float cx0 = g_cx2[r0], cx1 = g_cx2[r1];
        float inv_m0 = 1.f / fmaxf(1.f - cx0, 1e-15f);
        float inv_m1 = 1.f / fmaxf(1.f - cx1, 1e-15f);
        float onep0 = 1.f + cx0, onep1 = 1.f + cx1;
        float rs0 = 0.f, rs1 = 0.f;
#pragma unroll
        for (int nt = 0; nt < 8; nt++) {
            int col = colBlk + warp_n * 64 + nt * 8 + tig * 2;
            float4 p0 = g_colp[col];
            float4 p1 = g_colp[col + 1];
            float y00 = epi_y(acc[mt][nt][0], p0, onep0, inv_m0, inv_rc);
            float y01 = epi_y(acc[mt][nt][1], p1, onep0, inv_m0, inv_rc);
            float y10 = epi_y(acc[mt][nt][2], p0, onep1, inv_m1, inv_rc);
            float y11 = epi_y(acc[mt][nt][3], p1, onep1, inv_m1, inv_rc);
            *(float2*)(out + (size_t)r0 * OUT_DIM + col) = make_float2(y00, y01);
            *(float2*)(out + (size_t)r1 * OUT_DIM + col) = make_float2(y10, y11);
            rs0 = fmaf(y00, y00, fmaf(y01, y01, rs0));
            rs1 = fmaf(y10, y10, fmaf(y11, y11, rs1));
        }
        rs0 += __shfl_xor_sync(0xFFFFFFFFu, rs0, 1);
        rs0 += __shfl_xor_sync(0xFFFFFFFFu, rs0, 2);
        rs1 += __shfl_xor_sync(0xFFFFFFFFu, rs1, 1);
        rs1 += __shfl_xor_sync(0xFFFFFFFFu, rs1, 2);
        if (tig == 0) {
            atomicAdd(&g_rowsum[r0], rs0);
            atomicAdd(&g_rowsum[r1], rs1);
        }
    }
}

// ---------------------------------------------------------------------------
// Kernel D: per-row final scale.
// ---------------------------------------------------------------------------
__global__ void finalize_kernel(const float* __restrict__ cptr,
                                float* __restrict__ out) {
    int row = blockIdx.x;
    float c  = cptr[0];
    float rc = sqrtf(c);
    float s2 = g_rowsum[row];
    float denom = 1.f + sqrtf(fmaf(c, s2, 1.f));
    float scale = 1.f / denom;
    float nrm  = fmaxf(sqrtf(s2) * scale, 1e-15f);
    float maxn = (1.f - 0.004f) / rc;
    if (nrm > maxn) scale *= maxn / nrm;

    float4* o = (float4*)(out + (size_t)row * OUT_DIM);
    for (int idx = threadIdx.x; idx < OUT_DIM / 4; idx += blockDim.x) {
        float4 v = o[idx];
        v.x *= scale; v.y *= scale; v.z *= scale; v.w *= scale;
        o[idx] = v;
    }
}

// ---------------------------------------------------------------------------
extern "C" void kernel_launch(void* const* d_in, const int* in_sizes, int n_in,
                              void* d_out, int out_size) {
    const float* x    = (const float*)d_in[0];
    const float* wg   = (const float*)d_in[1];
    const float* wv   = (const float*)d_in[2];
    const float* bias = (const float*)d_in[3];
    const float* cptr = (const float*)d_in[4];
    float* out = (float*)d_out;

    double bni = exp(lgamma((double)IN_DIM / 2.0) + lgamma(0.5) -
                     lgamma((double)IN_DIM / 2.0 + 0.5));
    double bn  = exp(lgamma((double)(IN_DIM * IN_STACKS) / 2.0) + lgamma(0.5) -
                     lgamma((double)(IN_DIM * IN_STACKS) / 2.0 + 0.5));
    float ratio = (float)(bn / bni);

    static int smem_set = 0;
    if (!smem_set) {
        cudaFuncSetAttribute(gemm_mma_kernel,
                             cudaFuncAttributeMaxDynamicSharedMemorySize, SMEM_TOTAL);
        smem_set = 1;
    }

    colparams_kernel<<<OUT_DIM / 256, 256>>>(wv, wg, bias, cptr);
    preprocess_kernel<<<N_TOK, 256>>>(x, cptr, ratio);
    wsplit_kernel<<<dim3(OUT_DIM / 32, KDIM / 32), dim3(32, 8)>>>(wv);
    dim3 grid(OUT_DIM / BN, N_TOK / BM);
    gemm_mma_kernel<<<grid, 256, SMEM_TOTAL>>>(cptr, out);
    finalize_kernel<<<N_TOK, 256>>>(cptr, out);
}